// round 11
// baseline (speedup 1.0000x reference)
#include <cuda_runtime.h>
#include <cuda_fp16.h>
#include <cstdint>

// ---------------------------------------------------------------------------
// Problem constants
// ---------------------------------------------------------------------------
namespace {
constexpr int IN_F    = 4096;
constexpr int OUT_F   = 4096;
constexpr int RANK    = 16;
constexpr int M_TOTAL = 8192;            // 4 * 2048 tokens
constexpr float SCALING = 32.0f / 16.0f; // alpha / rank

// GEMM tiling: 128x128 CTA tile, 2 CTAs/SM so co-resident CTAs cover each
// other's barrier/LDSM-burst tensor-idle (the measured 12% gap at 1 CTA/SM).
constexpr int BM = 128, BN = 128, BK = 64;
constexpr int NKT = IN_F / BK;           // 64 k-tiles
constexpr int STAGES = 3;
constexpr int A_BYTES = BM * BK * 2;     // 16 KB
constexpr int B_BYTES = BN * BK * 2;     // 16 KB
constexpr int STAGE_BYTES = A_BYTES + B_BYTES;      // 32 KB
constexpr int SMEM_BYTES  = STAGES * STAGE_BYTES;   // 96 KB (x2 CTA = 192 KB/SM)
}  // namespace

// Scratch (device-global arrays: the sanctioned no-alloc workaround)
__device__ __align__(16) __half g_wh[(size_t)OUT_F * IN_F];   // W + (a/r)B@A, fp16
__device__ __align__(16) __half g_xh[(size_t)M_TOTAL * IN_F]; // x, fp16

// ---------------------------------------------------------------------------
// PTX helpers (all sm_80-compatible; nothing arch-accelerated)
// ---------------------------------------------------------------------------
__device__ __forceinline__ uint32_t smem_u32(const void* p) {
    uint32_t a;
    asm("{ .reg .u64 t; cvta.to.shared.u64 t, %1; cvt.u32.u64 %0, t; }"
        : "=r"(a) : "l"(p));
    return a;
}

__device__ __forceinline__ uint32_t swz128(uint32_t bo) {  // SW128 swizzle
    return bo ^ ((bo >> 3) & 0x70u);
}

__device__ __forceinline__ void cp_async16(uint32_t smem, const void* gmem) {
    asm volatile("cp.async.cg.shared.global [%0], [%1], 16;"
                 :: "r"(smem), "l"(gmem) : "memory");
}
#define CP_COMMIT() asm volatile("cp.async.commit_group;" ::: "memory")
#define CP_WAIT(n)  asm volatile("cp.async.wait_group %0;" :: "n"(n) : "memory")

__device__ __forceinline__ void ldsm_x4(uint32_t* r, uint32_t addr) {
    asm volatile("ldmatrix.sync.aligned.m8n8.x4.shared.b16 {%0,%1,%2,%3}, [%4];"
                 : "=r"(r[0]), "=r"(r[1]), "=r"(r[2]), "=r"(r[3]) : "r"(addr));
}

__device__ __forceinline__ void mma16816(float* d, const uint32_t* a,
                                         uint32_t b0, uint32_t b1) {
    asm volatile(
        "mma.sync.aligned.m16n8k16.row.col.f32.f16.f16.f32 "
        "{%0,%1,%2,%3}, {%4,%5,%6,%7}, {%8,%9}, {%0,%1,%2,%3};"
        : "+f"(d[0]), "+f"(d[1]), "+f"(d[2]), "+f"(d[3])
        : "r"(a[0]), "r"(a[1]), "r"(a[2]), "r"(a[3]), "r"(b0), "r"(b1));
}

__device__ __forceinline__ uint32_t half2_bits(__half2 h) {
    return *reinterpret_cast<uint32_t*>(&h);
}

// ---------------------------------------------------------------------------
// Prep 1: W_eff = W + scaling * B @ A -> fp16 (round-10 version, 30.4us)
// ---------------------------------------------------------------------------
__global__ void __launch_bounds__(256)
prep_w_kernel(const float* __restrict__ W, const float* __restrict__ A,
              const float* __restrict__ B) {
    const int i  = blockIdx.x * 512 + threadIdx.x * 2;
    const int o0 = blockIdx.y * 8;

    float2 wv[8];
#pragma unroll
    for (int oo = 0; oo < 8; ++oo)
        wv[oo] = *reinterpret_cast<const float2*>(W + (size_t)(o0 + oo) * IN_F + i);

    float2 af[RANK];
#pragma unroll
    for (int r = 0; r < RANK; ++r)
        af[r] = *reinterpret_cast<const float2*>(A + (size_t)r * IN_F + i);

#pragma unroll
    for (int oo = 0; oo < 8; ++oo) {
        const int o = o0 + oo;
        float2 acc = wv[oo];
        const float4* brow = reinterpret_cast<const float4*>(B + o * RANK);
#pragma unroll
        for (int rq = 0; rq < RANK / 4; ++rq) {
            const float4 bq = __ldg(brow + rq);   // warp-uniform, L1-hot
            const float bs[4] = {bq.x, bq.y, bq.z, bq.w};
#pragma unroll
            for (int j = 0; j < 4; ++j) {
                const float br = SCALING * bs[j];
                const float2 a2 = af[rq * 4 + j];
                acc.x = fmaf(br, a2.x, acc.x);
                acc.y = fmaf(br, a2.y, acc.y);
            }
        }
        *reinterpret_cast<uint32_t*>(&g_wh[(size_t)o * IN_F + i]) =
            half2_bits(__floats2half2_rn(acc.x, acc.y));
    }
}

// ---------------------------------------------------------------------------
// Prep 2: x -> fp16 (rn) — near HBM bandwidth; unchanged.
// ---------------------------------------------------------------------------
__global__ void __launch_bounds__(256)
prep_x_kernel(const float4* __restrict__ x) {
    const size_t idx = (size_t)blockIdx.x * 256 + threadIdx.x;  // 8 floats each
    float4 v0 = x[idx * 2], v1 = x[idx * 2 + 1];
    uint4 pack;
    pack.x = half2_bits(__floats2half2_rn(v0.x, v0.y));
    pack.y = half2_bits(__floats2half2_rn(v0.z, v0.w));
    pack.z = half2_bits(__floats2half2_rn(v1.x, v1.y));
    pack.w = half2_bits(__floats2half2_rn(v1.z, v1.w));
    reinterpret_cast<uint4*>(g_xh)[idx] = pack;
}

// ---------------------------------------------------------------------------
// Main GEMM: out[m,n] = sum_k g_xh[m,k]*g_wh[n,k] + bias[n]
// 128x128 CTA tile, BK=64, 3-stage cp.async, 2 CTAs/SM.
// 8 warps in 2(M) x 4(N): warp tile 64x32; acc 64 regs/thread so the kernel
// fits the 128-reg cap needed for dual occupancy.  Same register
// double-buffered ldmatrix pipeline as the measured rounds 6-10.
// ---------------------------------------------------------------------------
__global__ void __launch_bounds__(256, 2)
lora_gemm_kernel(const float* __restrict__ bias, float* __restrict__ out) {
    extern __shared__ char smem[];
    const uint32_t sbase = smem_u32(smem);
    const int tid  = threadIdx.x;
    const int lane = tid & 31;
    const int wid  = tid >> 5;
    const int m_base = blockIdx.y * BM;
    const int n_base = blockIdx.x * BN;
    const int wm = (wid & 1) * 64;   // warp M offset (2 warps over 128)
    const int wn = (wid >> 1) * 32;  // warp N offset (4 warps over 128)

    // ---- producer geometry: 16B chunks, 8 per 128B row ----
    const int pcol = tid & 7;        // 16B column within a row
    const int prow = tid >> 3;       // base row (0..31)
    uint32_t a_swz[4], b_swz[4];
#pragma unroll
    for (int i = 0; i < 4; ++i) {
        const uint32_t bo =
            (uint32_t)(prow + 32 * i) * 128u + (uint32_t)pcol * 16u;
        a_swz[i] = swz128(bo);
        b_swz[i] = A_BYTES + swz128(bo);
    }
    const __half* gA = g_xh + (size_t)(m_base + prow) * IN_F + pcol * 8;
    const __half* gB = g_wh + (size_t)(n_base + prow) * IN_F + pcol * 8;

    // ---- consumer geometry: ldmatrix lane addresses (swizzled, k0 base) ----
    // k-step advance must be XORed: swz(bo + ks*32) == swz(bo) ^ (ks*32).
    uint32_t sa_off[4], sb_off[2];
#pragma unroll
    for (int mi = 0; mi < 4; ++mi) {
        int r = wm + mi * 16 + (lane & 15);
        sa_off[mi] = swz128((uint32_t)r * 128u + ((uint32_t)(lane >> 4) * 16u));
    }
#pragma unroll
    for (int pj = 0; pj < 2; ++pj) {
        int r = wn + pj * 16 + (lane & 7) + ((lane >> 4) << 3);
        sb_off[pj] = A_BYTES +
                     swz128((uint32_t)r * 128u + (((uint32_t)(lane >> 3) & 1u) * 16u));
    }

    auto load_stage = [&](int slot, int kt) {
        const uint32_t ss = sbase + slot * STAGE_BYTES;
        const __half* ga = gA + kt * BK;
        const __half* gb = gB + kt * BK;
#pragma unroll
        for (int i = 0; i < 4; ++i)
            cp_async16(ss + a_swz[i], ga + (size_t)i * 32 * IN_F);
#pragma unroll
        for (int i = 0; i < 4; ++i)
            cp_async16(ss + b_swz[i], gb + (size_t)i * 32 * IN_F);
    };

    float acc[4][4][4] = {};           // 64 regs: 4 m16 x 4 n8
    uint32_t a[2][4][4], b[2][2][4];   // register double buffer (48 regs)

    // ---- prologue: fill STAGES-1 stages ----
#pragma unroll
    for (int s = 0; s < STAGES - 1; ++s) { load_stage(s, s); CP_COMMIT(); }
    CP_WAIT(STAGES - 2);
    __syncthreads();

    // preload ks=0 fragments of stage 0 into buffer 0
#pragma unroll
    for (int mi = 0; mi < 4; ++mi) ldsm_x4(a[0][mi], sbase + sa_off[mi]);
#pragma unroll
    for (int pj = 0; pj < 2; ++pj) ldsm_x4(b[0][pj], sbase + sb_off[pj]);

    int slot_c = 0;              // compute slot for kt
    int slot_l = STAGES - 1;     // load slot for kt+STAGES-1
#pragma unroll 1
    for (int kt = 0; kt < NKT; ++kt) {
        const int ld = kt + STAGES - 1;
        if (ld < NKT) load_stage(slot_l, ld);
        CP_COMMIT();  // empty group when ld >= NKT keeps wait bookkeeping simple
        if (++slot_l == STAGES) slot_l = 0;

        const uint32_t ss = sbase + slot_c * STAGE_BYTES;
        const int slot_n = (slot_c + 1 == STAGES) ? 0 : slot_c + 1;
#pragma unroll
        for (int ks = 0; ks < 4; ++ks) {
            const int cur = ks & 1, nxt = cur ^ 1;
            if (ks < 3) {
                // prefetch next k-step of this stage
                const uint32_t kx = (uint32_t)(ks + 1) * 32u;
#pragma unroll
                for (int mi = 0; mi < 4; ++mi)
                    ldsm_x4(a[nxt][mi], ss + (sa_off[mi] ^ kx));
#pragma unroll
                for (int pj = 0; pj < 2; ++pj)
                    ldsm_x4(b[nxt][pj], ss + (sb_off[pj] ^ kx));
            } else {
                // stage boundary: ensure next stage resident, then prefetch
                // its ks=0 fragments BEFORE the last MMA block of this stage
                CP_WAIT(STAGES - 2);
                __syncthreads();
                if (kt + 1 < NKT) {
                    const uint32_t ss2 = sbase + slot_n * STAGE_BYTES;
#pragma unroll
                    for (int mi = 0; mi < 4; ++mi)
                        ldsm_x4(a[nxt][mi], ss2 + sa_off[mi]);
#pragma unroll
                    for (int pj = 0; pj < 2; ++pj)
                        ldsm_x4(b[nxt][pj], ss2 + sb_off[pj]);
                }
            }
#pragma unroll
            for (int mi = 0; mi < 4; ++mi)
#pragma unroll
                for (int nj = 0; nj < 4; ++nj)
                    mma16816(acc[mi][nj], a[cur][mi],
                             b[cur][nj >> 1][(nj & 1) * 2],
                             b[cur][nj >> 1][(nj & 1) * 2 + 1]);
        }
        slot_c = slot_n;
    }

    // ---- epilogue: fp32 accum + bias -> gmem ----
    const int row0 = m_base + wm + (lane >> 2);
    const int col0 = n_base + wn + (lane & 3) * 2;
    float2 bv[4];
#pragma unroll
    for (int nj = 0; nj < 4; ++nj)
        bv[nj] = *reinterpret_cast<const float2*>(bias + col0 + nj * 8);
#pragma unroll
    for (int mi = 0; mi < 4; ++mi) {
        const int r = row0 + mi * 16;
#pragma unroll
        for (int nj = 0; nj < 4; ++nj) {
            const int c = col0 + nj * 8;
            float2 v0{acc[mi][nj][0] + bv[nj].x, acc[mi][nj][1] + bv[nj].y};
            float2 v1{acc[mi][nj][2] + bv[nj].x, acc[mi][nj][3] + bv[nj].y};
            *reinterpret_cast<float2*>(out + (size_t)r * OUT_F + c) = v0;
            *reinterpret_cast<float2*>(out + (size_t)(r + 8) * OUT_F + c) = v1;
        }
    }
}

// ---------------------------------------------------------------------------
// Entry point — bind inputs by element count (robust to metadata ordering):
//   x: 8192*4096 = 33554432, W: 4096*4096 = 16777216, b: 4096,
//   lora_A / lora_B: 65536 each (dataset order: A first).
// ---------------------------------------------------------------------------
extern "C" void kernel_launch(void* const* d_in, const int* in_sizes, int n_in,
                              void* d_out, int out_size) {
    const float *x = nullptr, *W = nullptr, *b = nullptr,
                *lA = nullptr, *lB = nullptr;
    for (int i = 0; i < n_in; ++i) {
        const float* p = (const float*)d_in[i];
        const long long sz = in_sizes[i];
        if (sz == (long long)M_TOTAL * IN_F)      x = p;
        else if (sz == (long long)OUT_F * IN_F)   W = p;
        else if (sz == OUT_F)                     b = p;
        else if (sz == RANK * IN_F) { if (!lA) lA = p; else lB = p; }
    }
    float* out = (float*)d_out;

    prep_w_kernel<<<dim3(IN_F / 512, OUT_F / 8), 256>>>(W, lA, lB);
    prep_x_kernel<<<(M_TOTAL * IN_F / 8) / 256, 256>>>((const float4*)x);

    cudaFuncSetAttribute(lora_gemm_kernel,
                         cudaFuncAttributeMaxDynamicSharedMemorySize, SMEM_BYTES);
    lora_gemm_kernel<<<dim3(OUT_F / BN, M_TOTAL / BM), 256, SMEM_BYTES>>>(b, out);
}

// round 12
// speedup vs baseline: 1.7621x; 1.7621x over previous
#include <cuda_runtime.h>
#include <cuda_fp16.h>
#include <cstdint>

// ---------------------------------------------------------------------------
// Problem constants
// ---------------------------------------------------------------------------
namespace {
constexpr int IN_F    = 4096;
constexpr int OUT_F   = 4096;
constexpr int RANK    = 16;
constexpr int M_TOTAL = 8192;            // 4 * 2048 tokens
constexpr float SCALING = 32.0f / 16.0f; // alpha / rank

// GEMM tiling: 128x128 CTA tile with 128-thread CTAs, 2 CTAs/SM.
// Dual occupancy comes from the small CTA (reg cap 256 -> NO spills, unlike
// round 11's 256-thread/128-reg attempt).  Per SMSP: 2 warps from DIFFERENT
// CTAs -> independent barriers cover each other's stage-boundary stalls.
constexpr int BM = 128, BN = 128, BK = 64;
constexpr int NKT = IN_F / BK;           // 64 k-tiles
constexpr int STAGES = 3;
constexpr int A_BYTES = BM * BK * 2;     // 16 KB
constexpr int B_BYTES = BN * BK * 2;     // 16 KB
constexpr int STAGE_BYTES = A_BYTES + B_BYTES;      // 32 KB
constexpr int SMEM_BYTES  = STAGES * STAGE_BYTES;   // 96 KB (x2 CTA = 192 KB/SM)
}  // namespace

// Scratch (device-global arrays: the sanctioned no-alloc workaround)
__device__ __align__(16) __half g_wh[(size_t)OUT_F * IN_F];   // W + (a/r)B@A, fp16
__device__ __align__(16) __half g_xh[(size_t)M_TOTAL * IN_F]; // x, fp16

// ---------------------------------------------------------------------------
// PTX helpers (all sm_80-compatible; nothing arch-accelerated)
// ---------------------------------------------------------------------------
__device__ __forceinline__ uint32_t smem_u32(const void* p) {
    uint32_t a;
    asm("{ .reg .u64 t; cvta.to.shared.u64 t, %1; cvt.u32.u64 %0, t; }"
        : "=r"(a) : "l"(p));
    return a;
}

__device__ __forceinline__ uint32_t swz128(uint32_t bo) {  // SW128 swizzle
    return bo ^ ((bo >> 3) & 0x70u);
}

__device__ __forceinline__ void cp_async16(uint32_t smem, const void* gmem) {
    asm volatile("cp.async.cg.shared.global [%0], [%1], 16;"
                 :: "r"(smem), "l"(gmem) : "memory");
}
#define CP_COMMIT() asm volatile("cp.async.commit_group;" ::: "memory")
#define CP_WAIT(n)  asm volatile("cp.async.wait_group %0;" :: "n"(n) : "memory")

__device__ __forceinline__ void ldsm_x4(uint32_t* r, uint32_t addr) {
    asm volatile("ldmatrix.sync.aligned.m8n8.x4.shared.b16 {%0,%1,%2,%3}, [%4];"
                 : "=r"(r[0]), "=r"(r[1]), "=r"(r[2]), "=r"(r[3]) : "r"(addr));
}

__device__ __forceinline__ void mma16816(float* d, const uint32_t* a,
                                         uint32_t b0, uint32_t b1) {
    asm volatile(
        "mma.sync.aligned.m16n8k16.row.col.f32.f16.f16.f32 "
        "{%0,%1,%2,%3}, {%4,%5,%6,%7}, {%8,%9}, {%0,%1,%2,%3};"
        : "+f"(d[0]), "+f"(d[1]), "+f"(d[2]), "+f"(d[3])
        : "r"(a[0]), "r"(a[1]), "r"(a[2]), "r"(a[3]), "r"(b0), "r"(b1));
}

__device__ __forceinline__ uint32_t half2_bits(__half2 h) {
    return *reinterpret_cast<uint32_t*>(&h);
}

// ---------------------------------------------------------------------------
// Prep 1: W_eff = W + scaling * B @ A -> fp16 (round-10 version, ~30us)
// ---------------------------------------------------------------------------
__global__ void __launch_bounds__(256)
prep_w_kernel(const float* __restrict__ W, const float* __restrict__ A,
              const float* __restrict__ B) {
    const int i  = blockIdx.x * 512 + threadIdx.x * 2;
    const int o0 = blockIdx.y * 8;

    float2 wv[8];
#pragma unroll
    for (int oo = 0; oo < 8; ++oo)
        wv[oo] = *reinterpret_cast<const float2*>(W + (size_t)(o0 + oo) * IN_F + i);

    float2 af[RANK];
#pragma unroll
    for (int r = 0; r < RANK; ++r)
        af[r] = *reinterpret_cast<const float2*>(A + (size_t)r * IN_F + i);

#pragma unroll
    for (int oo = 0; oo < 8; ++oo) {
        const int o = o0 + oo;
        float2 acc = wv[oo];
        const float4* brow = reinterpret_cast<const float4*>(B + o * RANK);
#pragma unroll
        for (int rq = 0; rq < RANK / 4; ++rq) {
            const float4 bq = __ldg(brow + rq);   // warp-uniform, L1-hot
            const float bs[4] = {bq.x, bq.y, bq.z, bq.w};
#pragma unroll
            for (int j = 0; j < 4; ++j) {
                const float br = SCALING * bs[j];
                const float2 a2 = af[rq * 4 + j];
                acc.x = fmaf(br, a2.x, acc.x);
                acc.y = fmaf(br, a2.y, acc.y);
            }
        }
        *reinterpret_cast<uint32_t*>(&g_wh[(size_t)o * IN_F + i]) =
            half2_bits(__floats2half2_rn(acc.x, acc.y));
    }
}

// ---------------------------------------------------------------------------
// Prep 2: x -> fp16 (rn) — near HBM bandwidth; unchanged.
// ---------------------------------------------------------------------------
__global__ void __launch_bounds__(256)
prep_x_kernel(const float4* __restrict__ x) {
    const size_t idx = (size_t)blockIdx.x * 256 + threadIdx.x;  // 8 floats each
    float4 v0 = x[idx * 2], v1 = x[idx * 2 + 1];
    uint4 pack;
    pack.x = half2_bits(__floats2half2_rn(v0.x, v0.y));
    pack.y = half2_bits(__floats2half2_rn(v0.z, v0.w));
    pack.z = half2_bits(__floats2half2_rn(v1.x, v1.y));
    pack.w = half2_bits(__floats2half2_rn(v1.z, v1.w));
    reinterpret_cast<uint4*>(g_xh)[idx] = pack;
}

// ---------------------------------------------------------------------------
// Main GEMM: out[m,n] = sum_k g_xh[m,k]*g_wh[n,k] + bias[n]
// 128x128 CTA tile, 128 threads (4 warps, 2Mx2N of 64x64), BK=64,
// 3-stage cp.async, 2 CTAs/SM.  Same register double-buffered ldmatrix
// pipeline and 8-LDSM-per-32-MMA ratio as the measured round-8 loop.
// ---------------------------------------------------------------------------
__global__ void __launch_bounds__(128, 2)
lora_gemm_kernel(const float* __restrict__ bias, float* __restrict__ out) {
    extern __shared__ char smem[];
    const uint32_t sbase = smem_u32(smem);
    const int tid  = threadIdx.x;
    const int lane = tid & 31;
    const int wid  = tid >> 5;                 // 0..3
    const int m_base = blockIdx.y * BM;
    const int n_base = blockIdx.x * BN;
    const int wm = (wid & 1) * 64;   // warp M offset (2 warps over 128)
    const int wn = (wid >> 1) * 64;  // warp N offset (2 warps over 128)

    // ---- producer geometry: 16B chunks, 8 per 128B row; 128 threads ----
    const int pcol = tid & 7;        // 16B column within a row
    const int prow = tid >> 3;       // base row (0..15)
    uint32_t a_swz[8], b_swz[8];
#pragma unroll
    for (int i = 0; i < 8; ++i) {
        const uint32_t bo =
            (uint32_t)(prow + 16 * i) * 128u + (uint32_t)pcol * 16u;
        a_swz[i] = swz128(bo);
        b_swz[i] = A_BYTES + swz128(bo);
    }
    const __half* gA = g_xh + (size_t)(m_base + prow) * IN_F + pcol * 8;
    const __half* gB = g_wh + (size_t)(n_base + prow) * IN_F + pcol * 8;

    // ---- consumer geometry: ldmatrix lane addresses (swizzled, k0 base) ----
    // k-step advance must be XORed: swz(bo + ks*32) == swz(bo) ^ (ks*32).
    uint32_t sa_off[4], sb_off[4];
#pragma unroll
    for (int mi = 0; mi < 4; ++mi) {
        int r = wm + mi * 16 + (lane & 15);
        sa_off[mi] = swz128((uint32_t)r * 128u + ((uint32_t)(lane >> 4) * 16u));
    }
#pragma unroll
    for (int pj = 0; pj < 4; ++pj) {
        int r = wn + pj * 16 + (lane & 7) + ((lane >> 4) << 3);
        sb_off[pj] = A_BYTES +
                     swz128((uint32_t)r * 128u + (((uint32_t)(lane >> 3) & 1u) * 16u));
    }

    auto load_stage = [&](int slot, int kt) {
        const uint32_t ss = sbase + slot * STAGE_BYTES;
        const __half* ga = gA + kt * BK;
        const __half* gb = gB + kt * BK;
#pragma unroll
        for (int i = 0; i < 8; ++i)
            cp_async16(ss + a_swz[i], ga + (size_t)i * 16 * IN_F);
#pragma unroll
        for (int i = 0; i < 8; ++i)
            cp_async16(ss + b_swz[i], gb + (size_t)i * 16 * IN_F);
    };

    float acc[4][8][4] = {};           // 128 regs: 4 m16 x 8 n8 (64x64 tile)
    uint32_t a[2][4][4], b[2][4][4];   // register double buffer (64 regs)

    // ---- prologue: fill STAGES-1 stages ----
#pragma unroll
    for (int s = 0; s < STAGES - 1; ++s) { load_stage(s, s); CP_COMMIT(); }
    CP_WAIT(STAGES - 2);
    __syncthreads();

    // preload ks=0 fragments of stage 0 into buffer 0
#pragma unroll
    for (int mi = 0; mi < 4; ++mi) ldsm_x4(a[0][mi], sbase + sa_off[mi]);
#pragma unroll
    for (int pj = 0; pj < 4; ++pj) ldsm_x4(b[0][pj], sbase + sb_off[pj]);

    int slot_c = 0;              // compute slot for kt
    int slot_l = STAGES - 1;     // load slot for kt+STAGES-1
#pragma unroll 1
    for (int kt = 0; kt < NKT; ++kt) {
        const int ld = kt + STAGES - 1;
        if (ld < NKT) load_stage(slot_l, ld);
        CP_COMMIT();  // empty group when ld >= NKT keeps wait bookkeeping simple
        if (++slot_l == STAGES) slot_l = 0;

        const uint32_t ss = sbase + slot_c * STAGE_BYTES;
        const int slot_n = (slot_c + 1 == STAGES) ? 0 : slot_c + 1;
#pragma unroll
        for (int ks = 0; ks < 4; ++ks) {
            const int cur = ks & 1, nxt = cur ^ 1;
            if (ks < 3) {
                // prefetch next k-step of this stage
                const uint32_t kx = (uint32_t)(ks + 1) * 32u;
#pragma unroll
                for (int mi = 0; mi < 4; ++mi)
                    ldsm_x4(a[nxt][mi], ss + (sa_off[mi] ^ kx));
#pragma unroll
                for (int pj = 0; pj < 4; ++pj)
                    ldsm_x4(b[nxt][pj], ss + (sb_off[pj] ^ kx));
            } else {
                // stage boundary: ensure next stage resident, then prefetch
                // its ks=0 fragments BEFORE the last MMA block of this stage
                CP_WAIT(STAGES - 2);
                __syncthreads();
                if (kt + 1 < NKT) {
                    const uint32_t ss2 = sbase + slot_n * STAGE_BYTES;
#pragma unroll
                    for (int mi = 0; mi < 4; ++mi)
                        ldsm_x4(a[nxt][mi], ss2 + sa_off[mi]);
#pragma unroll
                    for (int pj = 0; pj < 4; ++pj)
                        ldsm_x4(b[nxt][pj], ss2 + sb_off[pj]);
                }
            }
#pragma unroll
            for (int mi = 0; mi < 4; ++mi)
#pragma unroll
                for (int nj = 0; nj < 8; ++nj)
                    mma16816(acc[mi][nj], a[cur][mi],
                             b[cur][nj >> 1][(nj & 1) * 2],
                             b[cur][nj >> 1][(nj & 1) * 2 + 1]);
        }
        slot_c = slot_n;
    }

    // ---- epilogue: fp32 accum + bias -> gmem ----
    const int row0 = m_base + wm + (lane >> 2);
    const int col0 = n_base + wn + (lane & 3) * 2;
    float2 bv[8];
#pragma unroll
    for (int nj = 0; nj < 8; ++nj)
        bv[nj] = *reinterpret_cast<const float2*>(bias + col0 + nj * 8);
#pragma unroll
    for (int mi = 0; mi < 4; ++mi) {
        const int r = row0 + mi * 16;
#pragma unroll
        for (int nj = 0; nj < 8; ++nj) {
            const int c = col0 + nj * 8;
            float2 v0{acc[mi][nj][0] + bv[nj].x, acc[mi][nj][1] + bv[nj].y};
            float2 v1{acc[mi][nj][2] + bv[nj].x, acc[mi][nj][3] + bv[nj].y};
            *reinterpret_cast<float2*>(out + (size_t)r * OUT_F + c) = v0;
            *reinterpret_cast<float2*>(out + (size_t)(r + 8) * OUT_F + c) = v1;
        }
    }
}

// ---------------------------------------------------------------------------
// Entry point — bind inputs by element count (robust to metadata ordering):
//   x: 8192*4096 = 33554432, W: 4096*4096 = 16777216, b: 4096,
//   lora_A / lora_B: 65536 each (dataset order: A first).
// ---------------------------------------------------------------------------
extern "C" void kernel_launch(void* const* d_in, const int* in_sizes, int n_in,
                              void* d_out, int out_size) {
    const float *x = nullptr, *W = nullptr, *b = nullptr,
                *lA = nullptr, *lB = nullptr;
    for (int i = 0; i < n_in; ++i) {
        const float* p = (const float*)d_in[i];
        const long long sz = in_sizes[i];
        if (sz == (long long)M_TOTAL * IN_F)      x = p;
        else if (sz == (long long)OUT_F * IN_F)   W = p;
        else if (sz == OUT_F)                     b = p;
        else if (sz == RANK * IN_F) { if (!lA) lA = p; else lB = p; }
    }
    float* out = (float*)d_out;

    prep_w_kernel<<<dim3(IN_F / 512, OUT_F / 8), 256>>>(W, lA, lB);
    prep_x_kernel<<<(M_TOTAL * IN_F / 8) / 256, 256>>>((const float4*)x);

    cudaFuncSetAttribute(lora_gemm_kernel,
                         cudaFuncAttributeMaxDynamicSharedMemorySize, SMEM_BYTES);
    lora_gemm_kernel<<<dim3(OUT_F / BN, M_TOTAL / BM), 128, SMEM_BYTES>>>(b, out);
}